// round 12
// baseline (speedup 1.0000x reference)
#include <cuda_runtime.h>
#include <math.h>

// ChamferLoss: B=8, N=M=4096, D=3 — 2D snake-grid sort + one-warp-per-cell pruned NN.

#define BATCH    8
#define NPTS     4096
#define NCLOUD   16
#define GRID     32
#define NCELL    (GRID * GRID)          // 1024
#define XMIN     (-3.2f)
#define CELLW    0.2f
#define INV_CELLW 5.0f
#define S_THREADS 512
#define WPB       (S_THREADS / 32)      // 16 warps = 16 cells per block
#define BLK_PER_COMBO (NCELL / WPB)     // 64
#define NCOMBO   16
#define NBLOCKS  (NCOMBO * BLK_PER_COMBO)   // 1024

__device__ float4 g_sorted[NCLOUD][NPTS];        // (x,y,z,|p|^2), snake-cell-sorted
__device__ int    g_cellstart[NCLOUD][NCELL + 1];
__device__ double g_sum  = 0.0;
__device__ unsigned int g_tick = 0;

static __device__ __forceinline__ int clampg(int v) { return min(max(v, 0), GRID - 1); }
static __device__ __forceinline__ int cell_of(float x, float y) {
    int cx = clampg((int)((x - XMIN) * INV_CELLW));
    int cy = clampg((int)((y - XMIN) * INV_CELLW));
    int cxs = (cy & 1) ? (GRID - 1 - cx) : cx;   // snake: odd rows reversed
    return (cy << 5) | cxs;
}

// ---------------- Kernel 1: snake-cell counting sort, one block per cloud ----------------
__global__ __launch_bounds__(512) void sort_kernel(
    const float* __restrict__ pred,
    const float* __restrict__ targ)
{
    __shared__ int cnt[NCELL];
    __shared__ int ofs[NCELL];
    __shared__ int wtot[16];

    const int c = blockIdx.x;
    const int b = c >> 1;
    const float* __restrict__ src = ((c & 1) ? targ : pred) + (size_t)b * NPTS * 3;
    const int tid = threadIdx.x;

    for (int k = tid; k < NCELL; k += 512) cnt[k] = 0;
    __syncthreads();
    #pragma unroll
    for (int i = tid; i < NPTS; i += 512)
        atomicAdd(&cnt[cell_of(src[3 * i], src[3 * i + 1])], 1);
    __syncthreads();

    // Exclusive prefix over 1024 cells: 2 per thread + warp scan + cross-warp
    {
        const int base = tid * 2;
        int c0 = cnt[base], c1 = cnt[base + 1];
        int tot = c0 + c1;
        int inc = tot;
        #pragma unroll
        for (int o = 1; o < 32; o <<= 1) {
            int n = __shfl_up_sync(0xFFFFFFFFu, inc, o);
            if ((tid & 31) >= o) inc += n;
        }
        if ((tid & 31) == 31) wtot[tid >> 5] = inc;
        __syncthreads();
        if (tid == 0) {
            int r = 0;
            #pragma unroll
            for (int w = 0; w < 16; w++) { int t = wtot[w]; wtot[w] = r; r += t; }
        }
        __syncthreads();
        int off = (inc - tot) + wtot[tid >> 5];
        ofs[base] = off;          ofs[base + 1] = off + c0;
        g_cellstart[c][base] = off; g_cellstart[c][base + 1] = off + c0;
        if (tid == 511) g_cellstart[c][NCELL] = off + tot;
    }
    __syncthreads();

    #pragma unroll
    for (int i = tid; i < NPTS; i += 512) {
        float x = src[3 * i], y = src[3 * i + 1], z = src[3 * i + 2];
        float w = fmaf(x, x, fmaf(y, y, z * z));
        int pos = atomicAdd(&ofs[cell_of(x, y)], 1);
        g_sorted[c][pos] = make_float4(x, y, z, w);
    }
}

// ---------------- Kernel 2: one warp per source cell ----------------
__global__ __launch_bounds__(S_THREADS, 3) void search_kernel(float* __restrict__ out)
{
    __shared__ float warpsums[WPB];
    __shared__ unsigned int s_done;

    const int tid  = threadIdx.x;
    const int lane = tid & 31;
    const int wid  = tid >> 5;

    const int combo = blockIdx.x / BLK_PER_COMBO;
    const int cell  = (blockIdx.x % BLK_PER_COMBO) * WPB + wid;   // snake index
    const int b     = combo >> 1;
    const int dir   = combo & 1;
    const int cs    = b * 2 + dir;
    const int ct    = b * 2 + (dir ^ 1);

    const float4* __restrict__ tgt = g_sorted[ct];
    const int*    __restrict__ cst = g_cellstart[ct];

    // Geometric cell coords from snake index
    const int cy  = cell >> 5;
    const int cxs = cell & 31;
    const int cx  = (cy & 1) ? (GRID - 1 - cxs) : cxs;

    const int s0 = g_cellstart[cs][cell];
    const int s1 = g_cellstart[cs][cell + 1];

    const int wx0 = max(cx - 1, 0), wx1 = min(cx + 1, GRID - 1);
    const int wy0 = max(cy - 1, 0), wy1 = min(cy + 1, GRID - 1);

    float sacc = 0.0f;

    for (int base = s0; base < s1; base += 32) {          // usually 1 chunk
        const int  idx   = min(base + lane, s1 - 1);
        const bool valid = (base + lane) < s1;
        const float4 p = __ldg(&g_sorted[cs][idx]);
        const float mx = -2.0f * p.x, my = -2.0f * p.y, mz = -2.0f * p.z;
        float bestA = INFINITY, bestB = INFINITY;

        // Broadcast scan of rectangular cell window (snake rows contiguous)
        auto scan_win = [&](int ax0, int ax1, int ay0, int ay1) {
            for (int ry = ay0; ry <= ay1; ry++) {
                int a = (ry & 1) ? (GRID - 1 - ax1) : ax0;
                int e = (ry & 1) ? (GRID - 1 - ax0) : ax1;
                int j0 = __ldg(&cst[(ry << 5) + a]);
                int j1 = __ldg(&cst[(ry << 5) + e + 1]);
                int j = j0;
                for (; j + 1 < j1; j += 2) {
                    float4 t0 = __ldg(&tgt[j]);
                    float4 t1 = __ldg(&tgt[j + 1]);
                    bestA = fminf(bestA, fmaf(mx, t0.x, fmaf(my, t0.y, fmaf(mz, t0.z, t0.w))));
                    bestB = fminf(bestB, fmaf(mx, t1.x, fmaf(my, t1.y, fmaf(mz, t1.z, t1.w))));
                }
                if (j < j1) {
                    float4 t0 = __ldg(&tgt[j]);
                    bestA = fminf(bestA, fmaf(mx, t0.x, fmaf(my, t0.y, fmaf(mz, t0.z, t0.w))));
                }
            }
        };

        // Phase A: own cell + 1 ring
        scan_win(wx0, wx1, wy0, wy1);
        float d = sqrtf(fmaxf(fminf(bestA, bestB) + p.w, 0.0f));

        // Phase B: only if bound ball can escape the scanned window
        float mgl = (wx0 == 0)        ? 1e30f : p.x - (XMIN + wx0 * CELLW);
        float mgr = (wx1 == GRID - 1) ? 1e30f : (XMIN + (wx1 + 1) * CELLW) - p.x;
        float mgb = (wy0 == 0)        ? 1e30f : p.y - (XMIN + wy0 * CELLW);
        float mgt = (wy1 == GRID - 1) ? 1e30f : (XMIN + (wy1 + 1) * CELLW) - p.y;
        float margin = fminf(fminf(mgl, mgr), fminf(mgb, mgt));

        if (__any_sync(0xFFFFFFFFu, d >= margin * 0.9999f)) {
            float dc = d * 1.0001f + 1e-6f;
            int fx0 = clampg((int)floorf((p.x - dc - XMIN) * INV_CELLW));
            int fx1 = clampg((int)floorf((p.x + dc - XMIN) * INV_CELLW));
            int fy0 = clampg((int)floorf((p.y - dc - XMIN) * INV_CELLW));
            int fy1 = clampg((int)floorf((p.y + dc - XMIN) * INV_CELLW));
            #pragma unroll
            for (int o = 16; o > 0; o >>= 1) {
                fx0 = min(fx0, __shfl_xor_sync(0xFFFFFFFFu, fx0, o));
                fx1 = max(fx1, __shfl_xor_sync(0xFFFFFFFFu, fx1, o));
                fy0 = min(fy0, __shfl_xor_sync(0xFFFFFFFFu, fy0, o));
                fy1 = max(fy1, __shfl_xor_sync(0xFFFFFFFFu, fy1, o));
            }
            fx0 = min(fx0, wx0); fx1 = max(fx1, wx1);
            fy0 = min(fy0, wy0); fy1 = max(fy1, wy1);
            scan_win(fx0, fx1, fy0, fy1);        // idempotent superset rescan
            d = sqrtf(fmaxf(fminf(bestA, bestB) + p.w, 0.0f));
        }

        sacc += valid ? d : 0.0f;
    }

    // Warp -> block -> global reduction
    #pragma unroll
    for (int o = 16; o > 0; o >>= 1)
        sacc += __shfl_xor_sync(0xFFFFFFFFu, sacc, o);
    if (lane == 0) warpsums[wid] = sacc;
    __syncthreads();
    if (tid == 0) {
        float v = 0.0f;
        #pragma unroll
        for (int k = 0; k < WPB; k++) v += warpsums[k];
        atomicAdd(&g_sum, (double)v / ((double)BATCH * (double)NPTS));
    }

    // Ticket: last block publishes + resets
    __threadfence();
    if (tid == 0) s_done = atomicAdd(&g_tick, 1u);
    __syncthreads();
    if (s_done == NBLOCKS - 1 && tid == 0) {
        double total = atomicAdd(&g_sum, 0.0);   // atomic read
        out[0] = (float)total;
        g_sum  = 0.0;
        g_tick = 0;
    }
}

extern "C" void kernel_launch(void* const* d_in, const int* in_sizes, int n_in,
                              void* d_out, int out_size) {
    const float* pred = (const float*)d_in[0];
    const float* targ = (const float*)d_in[1];
    float* out = (float*)d_out;

    sort_kernel<<<NCLOUD, 512>>>(pred, targ);
    search_kernel<<<NBLOCKS, S_THREADS>>>(out);
}

// round 13
// speedup vs baseline: 5.6250x; 5.6250x over previous
#include <cuda_runtime.h>
#include <math.h>

// ChamferLoss: B=8, N=M=4096, D=3 — snake-grid sort + per-cell warps, smem-staged pruned NN.

#define BATCH    8
#define NPTS     4096
#define NCLOUD   16
#define GRID     32
#define NCELL    (GRID * GRID)          // 1024
#define XMIN     (-3.2f)
#define CELLW    0.2f
#define INV_CELLW 5.0f
#define S_THREADS 512
#define WPB       (S_THREADS / 32)      // 16 warps
#define SLICES    8                     // blocks per combo
#define CELLS_PB  (NCELL / SLICES)      // 128 cells per block
#define NCOMBO    16
#define NBLOCKS   (NCOMBO * SLICES)     // 128

__device__ float4 g_sorted[NCLOUD][NPTS];        // (x,y,z,|p|^2), snake-cell-sorted
__device__ int    g_cellstart[NCLOUD][NCELL + 1];
__device__ double g_sum  = 0.0;
__device__ unsigned int g_tick = 0;

static __device__ __forceinline__ int clampg(int v) { return min(max(v, 0), GRID - 1); }
static __device__ __forceinline__ int cell_of(float x, float y) {
    int cx = clampg((int)((x - XMIN) * INV_CELLW));
    int cy = clampg((int)((y - XMIN) * INV_CELLW));
    int cxs = (cy & 1) ? (GRID - 1 - cx) : cx;   // snake: odd rows reversed
    return (cy << 5) | cxs;
}

// ---------------- Kernel 1: snake-cell counting sort, one block per cloud ----------------
__global__ __launch_bounds__(512) void sort_kernel(
    const float* __restrict__ pred,
    const float* __restrict__ targ)
{
    __shared__ int cnt[NCELL];
    __shared__ int ofs[NCELL];
    __shared__ int wtot[16];

    const int c = blockIdx.x;
    const int b = c >> 1;
    const float* __restrict__ src = ((c & 1) ? targ : pred) + (size_t)b * NPTS * 3;
    const int tid = threadIdx.x;

    for (int k = tid; k < NCELL; k += 512) cnt[k] = 0;
    __syncthreads();
    #pragma unroll
    for (int i = tid; i < NPTS; i += 512)
        atomicAdd(&cnt[cell_of(src[3 * i], src[3 * i + 1])], 1);
    __syncthreads();

    {   // exclusive prefix over 1024 cells
        const int base = tid * 2;
        int c0 = cnt[base], c1 = cnt[base + 1];
        int tot = c0 + c1;
        int inc = tot;
        #pragma unroll
        for (int o = 1; o < 32; o <<= 1) {
            int n = __shfl_up_sync(0xFFFFFFFFu, inc, o);
            if ((tid & 31) >= o) inc += n;
        }
        if ((tid & 31) == 31) wtot[tid >> 5] = inc;
        __syncthreads();
        if (tid == 0) {
            int r = 0;
            #pragma unroll
            for (int w = 0; w < 16; w++) { int t = wtot[w]; wtot[w] = r; r += t; }
        }
        __syncthreads();
        int off = (inc - tot) + wtot[tid >> 5];
        ofs[base] = off;            ofs[base + 1] = off + c0;
        g_cellstart[c][base] = off; g_cellstart[c][base + 1] = off + c0;
        if (tid == 511) g_cellstart[c][NCELL] = off + tot;
    }
    __syncthreads();

    #pragma unroll
    for (int i = tid; i < NPTS; i += 512) {
        float x = src[3 * i], y = src[3 * i + 1], z = src[3 * i + 2];
        float w = fmaf(x, x, fmaf(y, y, z * z));
        int pos = atomicAdd(&ofs[cell_of(x, y)], 1);
        g_sorted[c][pos] = make_float4(x, y, z, w);
    }
}

// ---------------- Kernel 2: per-cell warps over smem-staged cloud ----------------
struct Smem {
    float4 tgt[NPTS];            // 64 KB
    int    cst[NCELL + 1];       // 4.1 KB
    float  warpsums[WPB];
    unsigned int s_done;
};

__global__ __launch_bounds__(S_THREADS) void search_kernel(float* __restrict__ out)
{
    extern __shared__ char smem_raw[];
    Smem* s = (Smem*)smem_raw;
    const int tid  = threadIdx.x;
    const int lane = tid & 31;
    const int wid  = tid >> 5;

    const int combo = blockIdx.x / SLICES;
    const int slice = blockIdx.x % SLICES;
    const int b     = combo >> 1;
    const int dir   = combo & 1;
    const int cs    = b * 2 + dir;
    const int ct    = b * 2 + (dir ^ 1);

    // Stage sorted target cloud + cell prefix (coalesced)
    {
        const float4* __restrict__ g = g_sorted[ct];
        #pragma unroll
        for (int k = 0; k < NPTS / S_THREADS; k++)
            s->tgt[k * S_THREADS + tid] = g[k * S_THREADS + tid];
        for (int k = tid; k < NCELL + 1; k += S_THREADS)
            s->cst[k] = g_cellstart[ct][k];
    }
    __syncthreads();

    float sacc = 0.0f;

    // Each warp: 8 strided cells from this block's 128-cell slice
    for (int cc = wid; cc < CELLS_PB; cc += WPB) {
        const int cell = slice * CELLS_PB + cc;       // snake index
        const int cy   = cell >> 5;
        const int cxs  = cell & 31;
        const int cx   = (cy & 1) ? (GRID - 1 - cxs) : cxs;

        const int p0 = g_cellstart[cs][cell];
        const int p1 = g_cellstart[cs][cell + 1];
        if (p0 == p1) continue;

        for (int base = p0; base < p1; base += 32) {      // usually 1 chunk
            const int  idx   = min(base + lane, p1 - 1);
            const bool valid = (base + lane) < p1;
            const float4 p = __ldg(&g_sorted[cs][idx]);
            const float mx = -2.0f * p.x, my = -2.0f * p.y, mz = -2.0f * p.z;
            float bestA = INFINITY, bestB = INFINITY;

            // Broadcast scan of row-segments (snake rows contiguous in smem)
            auto scan_rows = [&](int ax0, int ax1, int ay0, int ay1) {
                for (int ry = ay0; ry <= ay1; ry++) {
                    int a = (ry & 1) ? (GRID - 1 - ax1) : ax0;
                    int e = (ry & 1) ? (GRID - 1 - ax0) : ax1;
                    int j0 = s->cst[(ry << 5) + a];
                    int j1 = s->cst[(ry << 5) + e + 1];
                    int j = j0;
                    for (; j + 1 < j1; j += 2) {
                        float4 t0 = s->tgt[j];
                        float4 t1 = s->tgt[j + 1];
                        bestA = fminf(bestA, fmaf(mx, t0.x, fmaf(my, t0.y, fmaf(mz, t0.z, t0.w))));
                        bestB = fminf(bestB, fmaf(mx, t1.x, fmaf(my, t1.y, fmaf(mz, t1.z, t1.w))));
                    }
                    if (j < j1) {
                        float4 t0 = s->tgt[j];
                        bestA = fminf(bestA, fmaf(mx, t0.x, fmaf(my, t0.y, fmaf(mz, t0.z, t0.w))));
                    }
                }
            };

            // Phase A: 3x3 ring; expand perimeter while empty (bounded, cheap)
            int wx0 = max(cx - 1, 0), wx1 = min(cx + 1, GRID - 1);
            int wy0 = max(cy - 1, 0), wy1 = min(cy + 1, GRID - 1);
            scan_rows(wx0, wx1, wy0, wy1);
            int r = 1;
            while (fminf(bestA, bestB) == INFINITY &&
                   !(wx0 == 0 && wx1 == GRID - 1 && wy0 == 0 && wy1 == GRID - 1)) {
                r++;
                int nx0 = max(cx - r, 0), nx1 = min(cx + r, GRID - 1);
                int ny0 = max(cy - r, 0), ny1 = min(cy + r, GRID - 1);
                if (ny0 < wy0) scan_rows(nx0, nx1, ny0, ny0);
                if (ny1 > wy1) scan_rows(nx0, nx1, ny1, ny1);
                if (nx0 < wx0) scan_rows(nx0, nx0, wy0, wy1);
                if (nx1 > wx1) scan_rows(nx1, nx1, wy0, wy1);
                wx0 = nx0; wx1 = nx1; wy0 = ny0; wy1 = ny1;
            }
            float d = sqrtf(fmaxf(fminf(bestA, bestB) + p.w, 0.0f));

            // Phase B: only if the bound ball can escape the scanned rectangle
            float mgl = (wx0 == 0)        ? 1e30f : p.x - (XMIN + wx0 * CELLW);
            float mgr = (wx1 == GRID - 1) ? 1e30f : (XMIN + (wx1 + 1) * CELLW) - p.x;
            float mgb = (wy0 == 0)        ? 1e30f : p.y - (XMIN + wy0 * CELLW);
            float mgt = (wy1 == GRID - 1) ? 1e30f : (XMIN + (wy1 + 1) * CELLW) - p.y;
            float margin = fminf(fminf(mgl, mgr), fminf(mgb, mgt));

            if (__any_sync(0xFFFFFFFFu, d >= margin * 0.9999f)) {
                float dc = d * 1.0001f + 1e-6f;
                int fx0 = clampg((int)floorf((p.x - dc - XMIN) * INV_CELLW));
                int fx1 = clampg((int)floorf((p.x + dc - XMIN) * INV_CELLW));
                int fy0 = clampg((int)floorf((p.y - dc - XMIN) * INV_CELLW));
                int fy1 = clampg((int)floorf((p.y + dc - XMIN) * INV_CELLW));
                #pragma unroll
                for (int o = 16; o > 0; o >>= 1) {
                    fx0 = min(fx0, __shfl_xor_sync(0xFFFFFFFFu, fx0, o));
                    fx1 = max(fx1, __shfl_xor_sync(0xFFFFFFFFu, fx1, o));
                    fy0 = min(fy0, __shfl_xor_sync(0xFFFFFFFFu, fy0, o));
                    fy1 = max(fy1, __shfl_xor_sync(0xFFFFFFFFu, fy1, o));
                }
                fx0 = min(fx0, wx0); fx1 = max(fx1, wx1);
                fy0 = min(fy0, wy0); fy1 = max(fy1, wy1);
                // Scan only the delta around the already-scanned rectangle
                for (int ry = fy0; ry <= fy1; ry++) {
                    if (ry < wy0 || ry > wy1) {
                        scan_rows(fx0, fx1, ry, ry);
                    } else {
                        if (fx0 < wx0) scan_rows(fx0, wx0 - 1, ry, ry);
                        if (fx1 > wx1) scan_rows(wx1 + 1, fx1, ry, ry);
                    }
                }
                d = sqrtf(fmaxf(fminf(bestA, bestB) + p.w, 0.0f));
            }

            sacc += valid ? d : 0.0f;
        }
    }

    // Warp -> block -> global reduction
    #pragma unroll
    for (int o = 16; o > 0; o >>= 1)
        sacc += __shfl_xor_sync(0xFFFFFFFFu, sacc, o);
    if (lane == 0) s->warpsums[wid] = sacc;
    __syncthreads();
    if (tid == 0) {
        float v = 0.0f;
        #pragma unroll
        for (int k = 0; k < WPB; k++) v += s->warpsums[k];
        atomicAdd(&g_sum, (double)v / ((double)BATCH * (double)NPTS));
    }

    // Ticket: last block publishes + resets
    __threadfence();
    if (tid == 0) s->s_done = atomicAdd(&g_tick, 1u);
    __syncthreads();
    if (s->s_done == NBLOCKS - 1 && tid == 0) {
        double total = atomicAdd(&g_sum, 0.0);   // atomic read
        out[0] = (float)total;
        g_sum  = 0.0;
        g_tick = 0;
    }
}

extern "C" void kernel_launch(void* const* d_in, const int* in_sizes, int n_in,
                              void* d_out, int out_size) {
    const float* pred = (const float*)d_in[0];
    const float* targ = (const float*)d_in[1];
    float* out = (float*)d_out;

    static bool attr_set = false;
    if (!attr_set) {
        cudaFuncSetAttribute(search_kernel,
                             cudaFuncAttributeMaxDynamicSharedMemorySize,
                             (int)sizeof(Smem));
        attr_set = true;
    }
    sort_kernel<<<NCLOUD, 512>>>(pred, targ);
    search_kernel<<<NBLOCKS, S_THREADS, sizeof(Smem)>>>(out);
}